// round 13
// baseline (speedup 1.0000x reference)
#include <cuda_runtime.h>
#include <cuda_bf16.h>

// RippleNet: H=2, B=2048, M=64, D=16, N_ENT=500000, N_REL=32
// inputs: items[B] i32, heads[H,B,M] i32, relations[H,B,M] i32,
//         tails[H,B,M] i32, ent_emb[N_ENT,16] f32, rel_emb[32,16,16] f32
// output: predicts[B] f32
//
// FINAL (R9 champion). Measured floor: ~33.5MB of irreducible random 64B row
// gathers at the DRAM scattered-access ceiling (~2.6TB/s) -> ~12.8us. Three
// orthogonal structures (register-gather, dual-b, cp.async+smem) all tie at
// this wall time; this variant has the best cold/contended ncu profile.

#define H_ 2
#define B_ 2048
#define M_ 64
#define D_ 16
#define NREL_ 32
#define QS 20   // q row stride in floats: float4-aligned, low bank conflict

// One block per b, 128 threads (proven best latency structure).
// Gathers: quad (4 lanes) = one 64B entity row; thread (quad,ch) owns rows
// {quad, quad+32, quad+64, quad+96}, 16B chunk ch -> one 128B line per quad
// per instruction (line-minimal wavefronts).
// q-phase: octet (8 lanes) = one rel; rows 2k+half -> one full 128B rel line
// per instruction (line-minimal), overlapped with in-flight gathers.
__global__ __launch_bounds__(128, 8) void ripple_kernel(
    const int* __restrict__ items,
    const int* __restrict__ heads,
    const int* __restrict__ rels,
    const int* __restrict__ tails,
    const float* __restrict__ ent,
    const float* __restrict__ rel,
    float* __restrict__ out)
{
    const int b    = blockIdx.x;
    const int tid  = threadIdx.x;
    const int quad = tid >> 2;
    const int ch   = tid & 3;
    const int j0   = ch * 4;

    __shared__ float  item_s[D_];
    __shared__ float  q[NREL_ * QS];
    __shared__ float4 wsum[4];        // per-warp {se0, ses0, se1, ses1}

    const int it = items[b];
    if (tid < D_) item_s[tid] = __ldg(ent + (size_t)it * D_ + tid);

    // ---- index loads (quad-broadcast; issue ASAP, gathers chain off them) ----
    int hidx[4], ridx[4], tidx[4];
    #pragma unroll
    for (int k = 0; k < 4; k++) {
        const int row  = quad + 32 * k;
        const int base = (row >> 6) * (B_ * M_) + b * M_ + (row & 63);
        hidx[k] = __ldg(heads + base);
        ridx[k] = __ldg(rels  + base);
        tidx[k] = __ldg(tails + base);
    }

    // ---- front-batch all embedding gathers (quad-coalesced, high MLP) ----
    const float4 vi = __ldg((const float4*)(ent + (size_t)it * D_ + j0));
    float4 hv[4], tv[4];
    #pragma unroll
    for (int k = 0; k < 4; k++)
        hv[k] = __ldg((const float4*)(ent + (size_t)hidx[k] * D_ + j0));
    #pragma unroll
    for (int k = 0; k < 4; k++)
        tv[k] = __ldg((const float4*)(ent + (size_t)tidx[k] * D_ + j0));

    __syncthreads();   // item_s ready; in-flight gathers keep flying

    // ---- q-phase, octet-coalesced: lane (ch,half) of octet O covers rel r,
    //      rows i = 2k + half. One 128B line per octet per step. ----
    {
        const int lane = tid & 31;
        const int O    = (tid >> 5) * 4 + ((lane >> 3) & 3);   // global octet 0..15
        const int half = (lane >> 2) & 1;

        #pragma unroll
        for (int rr = 0; rr < 2; rr++) {
            const int r = O + 16 * rr;                          // rels O, O+16
            const float4* Rp = (const float4*)(rel + r * (D_ * D_)) + ch;
            float4 acc = make_float4(0.f, 0.f, 0.f, 0.f);
            #pragma unroll
            for (int k = 0; k < 8; k++) {
                const int i = 2 * k + half;
                const float4 rv = Rp[i * 4];
                const float  wi = item_s[i];
                acc.x = fmaf(wi, rv.x, acc.x);
                acc.y = fmaf(wi, rv.y, acc.y);
                acc.z = fmaf(wi, rv.z, acc.z);
                acc.w = fmaf(wi, rv.w, acc.w);
            }
            // merge even/odd halves within the octet
            acc.x += __shfl_xor_sync(0xffffffffu, acc.x, 4);
            acc.y += __shfl_xor_sync(0xffffffffu, acc.y, 4);
            acc.z += __shfl_xor_sync(0xffffffffu, acc.z, 4);
            acc.w += __shfl_xor_sync(0xffffffffu, acc.w, 4);
            if (half == 0)
                *(float4*)&q[r * QS + j0] = acc;
        }
    }

    // ---- tail dots (independent of q; tv dies early) ----
    float s[4];
    #pragma unroll
    for (int k = 0; k < 4; k++) {
        float ps = fmaf(vi.x, tv[k].x, fmaf(vi.y, tv[k].y,
                   fmaf(vi.z, tv[k].z, vi.w * tv[k].w)));
        ps += __shfl_xor_sync(0xffffffffu, ps, 1);
        ps += __shfl_xor_sync(0xffffffffu, ps, 2);
        s[k] = ps;
    }

    __syncthreads();   // q ready

    // ---- head dots: logit via q[ridx] (LDS.128) ----
    float l[4];
    #pragma unroll
    for (int k = 0; k < 4; k++) {
        const float4 w = *(const float4*)&q[ridx[k] * QS + j0];
        float p = fmaf(w.x, hv[k].x, fmaf(w.y, hv[k].y,
                  fmaf(w.z, hv[k].z, w.w * hv[k].w)));
        p += __shfl_xor_sync(0xffffffffu, p, 1);
        p += __shfl_xor_sync(0xffffffffu, p, 2);
        l[k] = p;
    }

    // ---- softmax w/o max subtraction (|l| ~ 0.1; exp safe, identical math) ----
    const float e0 = __expf(l[0]), e1 = __expf(l[1]);
    const float e2 = __expf(l[2]), e3 = __expf(l[3]);
    float se0  = e0 + e1;
    float ses0 = fmaf(e0, s[0], e1 * s[1]);
    float se1  = e2 + e3;
    float ses1 = fmaf(e2, s[2], e3 * s[3]);

    // lanes within a quad hold identical values -> reduce offsets 16,8,4 only
    #pragma unroll
    for (int off = 16; off >= 4; off >>= 1) {
        se0  += __shfl_xor_sync(0xffffffffu, se0,  off);
        ses0 += __shfl_xor_sync(0xffffffffu, ses0, off);
        se1  += __shfl_xor_sync(0xffffffffu, se1,  off);
        ses1 += __shfl_xor_sync(0xffffffffu, ses1, off);
    }
    if ((tid & 31) == 0)
        wsum[tid >> 5] = make_float4(se0, ses0, se1, ses1);
    __syncthreads();

    if (tid == 0) {
        float SE0 = 0.f, SES0 = 0.f, SE1 = 0.f, SES1 = 0.f;
        #pragma unroll
        for (int i = 0; i < 4; i++) {
            const float4 v = wsum[i];
            SE0 += v.x; SES0 += v.y; SE1 += v.z; SES1 += v.w;
        }
        // 4x quad-lane replication cancels in each ratio
        const float x = SES0 / SE0 + SES1 / SE1;
        out[b] = 1.f / (1.f + __expf(-x));
    }
}

extern "C" void kernel_launch(void* const* d_in, const int* in_sizes, int n_in,
                              void* d_out, int out_size) {
    const int*   items = (const int*)  d_in[0];
    const int*   heads = (const int*)  d_in[1];
    const int*   rels  = (const int*)  d_in[2];
    const int*   tails = (const int*)  d_in[3];
    const float* ent   = (const float*)d_in[4];
    const float* rel   = (const float*)d_in[5];
    float* out = (float*)d_out;

    ripple_kernel<<<B_, 128>>>(items, heads, rels, tails, ent, rel, out);
}

// round 14
// speedup vs baseline: 1.0025x; 1.0025x over previous
#include <cuda_runtime.h>
#include <cuda_bf16.h>

// RippleNet: H=2, B=2048, M=64, D=16, N_ENT=500000, N_REL=32
// inputs: items[B] i32, heads[H,B,M] i32, relations[H,B,M] i32,
//         tails[H,B,M] i32, ent_emb[N_ENT,16] f32, rel_emb[32,16,16] f32
// output: predicts[B] f32
//
// FINAL (converged champion). Floor analysis: ~33.5MB of algorithmically
// irreducible random 64B row gathers served at ~2.4-2.6TB/s (the HBM3e
// activate-bound ceiling for scattered 64B granules) -> ~12.8us. Three
// orthogonal kernel structures tie at this wall time; all SM-side levers
// (wavefronts, occupancy, waves, L2 policy, cp.async, batching) tested.

#define H_ 2
#define B_ 2048
#define M_ 64
#define D_ 16
#define NREL_ 32
#define QS 20   // q row stride in floats: float4-aligned, low bank conflict

// One block per b, 128 threads.
// Gathers: quad (4 lanes) = one 64B entity row; thread (quad,ch) owns rows
// {quad, quad+32, quad+64, quad+96}, 16B chunk ch -> one 128B line per quad
// per instruction (line-minimal wavefronts).
// q-phase: octet (8 lanes) = one rel; rows 2k+half -> one full 128B rel line
// per instruction (line-minimal), overlapped with in-flight gathers.
__global__ __launch_bounds__(128, 8) void ripple_kernel(
    const int* __restrict__ items,
    const int* __restrict__ heads,
    const int* __restrict__ rels,
    const int* __restrict__ tails,
    const float* __restrict__ ent,
    const float* __restrict__ rel,
    float* __restrict__ out)
{
    const int b    = blockIdx.x;
    const int tid  = threadIdx.x;
    const int quad = tid >> 2;
    const int ch   = tid & 3;
    const int j0   = ch * 4;

    __shared__ float  item_s[D_];
    __shared__ float  q[NREL_ * QS];
    __shared__ float4 wsum[4];        // per-warp {se0, ses0, se1, ses1}

    const int it = items[b];
    if (tid < D_) item_s[tid] = __ldg(ent + (size_t)it * D_ + tid);

    // ---- index loads (quad-broadcast; issue ASAP, gathers chain off them) ----
    int hidx[4], ridx[4], tidx[4];
    #pragma unroll
    for (int k = 0; k < 4; k++) {
        const int row  = quad + 32 * k;
        const int base = (row >> 6) * (B_ * M_) + b * M_ + (row & 63);
        hidx[k] = __ldg(heads + base);
        ridx[k] = __ldg(rels  + base);
        tidx[k] = __ldg(tails + base);
    }

    // ---- front-batch all embedding gathers (quad-coalesced, high MLP) ----
    const float4 vi = __ldg((const float4*)(ent + (size_t)it * D_ + j0));
    float4 hv[4], tv[4];
    #pragma unroll
    for (int k = 0; k < 4; k++)
        hv[k] = __ldg((const float4*)(ent + (size_t)hidx[k] * D_ + j0));
    #pragma unroll
    for (int k = 0; k < 4; k++)
        tv[k] = __ldg((const float4*)(ent + (size_t)tidx[k] * D_ + j0));

    __syncthreads();   // item_s ready; in-flight gathers keep flying

    // ---- q-phase, octet-coalesced: lane (ch,half) of octet O covers rel r,
    //      rows i = 2k + half. One 128B line per octet per step. ----
    {
        const int lane = tid & 31;
        const int O    = (tid >> 5) * 4 + ((lane >> 3) & 3);   // global octet 0..15
        const int half = (lane >> 2) & 1;

        #pragma unroll
        for (int rr = 0; rr < 2; rr++) {
            const int r = O + 16 * rr;                          // rels O, O+16
            const float4* Rp = (const float4*)(rel + r * (D_ * D_)) + ch;
            float4 acc = make_float4(0.f, 0.f, 0.f, 0.f);
            #pragma unroll
            for (int k = 0; k < 8; k++) {
                const int i = 2 * k + half;
                const float4 rv = Rp[i * 4];
                const float  wi = item_s[i];
                acc.x = fmaf(wi, rv.x, acc.x);
                acc.y = fmaf(wi, rv.y, acc.y);
                acc.z = fmaf(wi, rv.z, acc.z);
                acc.w = fmaf(wi, rv.w, acc.w);
            }
            // merge even/odd halves within the octet
            acc.x += __shfl_xor_sync(0xffffffffu, acc.x, 4);
            acc.y += __shfl_xor_sync(0xffffffffu, acc.y, 4);
            acc.z += __shfl_xor_sync(0xffffffffu, acc.z, 4);
            acc.w += __shfl_xor_sync(0xffffffffu, acc.w, 4);
            if (half == 0)
                *(float4*)&q[r * QS + j0] = acc;
        }
    }

    // ---- tail dots (independent of q; tv dies early) ----
    float s[4];
    #pragma unroll
    for (int k = 0; k < 4; k++) {
        float ps = fmaf(vi.x, tv[k].x, fmaf(vi.y, tv[k].y,
                   fmaf(vi.z, tv[k].z, vi.w * tv[k].w)));
        ps += __shfl_xor_sync(0xffffffffu, ps, 1);
        ps += __shfl_xor_sync(0xffffffffu, ps, 2);
        s[k] = ps;
    }

    __syncthreads();   // q ready

    // ---- head dots: logit via q[ridx] (LDS.128) ----
    float l[4];
    #pragma unroll
    for (int k = 0; k < 4; k++) {
        const float4 w = *(const float4*)&q[ridx[k] * QS + j0];
        float p = fmaf(w.x, hv[k].x, fmaf(w.y, hv[k].y,
                  fmaf(w.z, hv[k].z, w.w * hv[k].w)));
        p += __shfl_xor_sync(0xffffffffu, p, 1);
        p += __shfl_xor_sync(0xffffffffu, p, 2);
        l[k] = p;
    }

    // ---- softmax w/o max subtraction (|l| ~ 0.1; exp safe, identical math) ----
    const float e0 = __expf(l[0]), e1 = __expf(l[1]);
    const float e2 = __expf(l[2]), e3 = __expf(l[3]);
    float se0  = e0 + e1;
    float ses0 = fmaf(e0, s[0], e1 * s[1]);
    float se1  = e2 + e3;
    float ses1 = fmaf(e2, s[2], e3 * s[3]);

    // lanes within a quad hold identical values -> reduce offsets 16,8,4 only
    #pragma unroll
    for (int off = 16; off >= 4; off >>= 1) {
        se0  += __shfl_xor_sync(0xffffffffu, se0,  off);
        ses0 += __shfl_xor_sync(0xffffffffu, ses0, off);
        se1  += __shfl_xor_sync(0xffffffffu, se1,  off);
        ses1 += __shfl_xor_sync(0xffffffffu, ses1, off);
    }
    if ((tid & 31) == 0)
        wsum[tid >> 5] = make_float4(se0, ses0, se1, ses1);
    __syncthreads();

    if (tid == 0) {
        float SE0 = 0.f, SES0 = 0.f, SE1 = 0.f, SES1 = 0.f;
        #pragma unroll
        for (int i = 0; i < 4; i++) {
            const float4 v = wsum[i];
            SE0 += v.x; SES0 += v.y; SE1 += v.z; SES1 += v.w;
        }
        // 4x quad-lane replication cancels in each ratio
        const float x = SES0 / SE0 + SES1 / SE1;
        out[b] = 1.f / (1.f + __expf(-x));
    }
}

extern "C" void kernel_launch(void* const* d_in, const int* in_sizes, int n_in,
                              void* d_out, int out_size) {
    const int*   items = (const int*)  d_in[0];
    const int*   heads = (const int*)  d_in[1];
    const int*   rels  = (const int*)  d_in[2];
    const int*   tails = (const int*)  d_in[3];
    const float* ent   = (const float*)d_in[4];
    const float* rel   = (const float*)d_in[5];
    float* out = (float*)d_out;

    ripple_kernel<<<B_, 128>>>(items, heads, rels, tails, ent, rel, out);
}